// round 15
// baseline (speedup 1.0000x reference)
#include <cuda_runtime.h>
#include <math.h>
#include <stdint.h>

#define NTOK 8192
#define DM   512
#define NE   8
#define TOPK 2
#define NASSIGN (NTOK * TOPK)

// ---------------- scratch (device globals: no allocation allowed) ----------------
__device__ int      g_count[NE];
__device__ int      g_offs[NE];
__device__ int      g_cursor[NE];
__device__ int      g_ts[NE + 1];                   // tile-index prefix per expert
__device__ int      g_ntiles;
__device__ int      g_tile_cursor;
__device__ int      g_eidx[NTOK][TOPK];
__device__ float    g_gate[NTOK][TOPK];
__device__ int      g_tok[NASSIGN];
__device__ int      g_slot[NTOK][TOPK];
__device__ float    g_y[(size_t)NASSIGN * DM];      // 32 MB expert-output scratch
__device__ unsigned g_wt[(size_t)NE * DM * DM];     // 8 MB: W^T tf32 bits [e][n][k]

// ---------------- helpers ----------------
__device__ __forceinline__ unsigned f2tf32(float f) {
    unsigned u;
    asm("cvt.rna.tf32.f32 %0, %1;" : "=r"(u) : "f"(f));
    return u;
}
__device__ __forceinline__ uint32_t smem_u32(const void* p) {
    uint32_t a;
    asm("{ .reg .u64 t; cvta.to.shared.u64 t, %1; cvt.u32.u64 %0, t; }" : "=r"(a) : "l"(p));
    return a;
}
__device__ __forceinline__ void cp16(uint32_t dst, const void* src) {
    asm volatile("cp.async.cg.shared.global [%0], [%1], 16;" :: "r"(dst), "l"(src));
}
#define CP_COMMIT() asm volatile("cp.async.commit_group;" ::: "memory")
#define CP_WAIT0()  asm volatile("cp.async.wait_group 0;" ::: "memory")

__device__ __forceinline__ void mma_tf32(float d[4], const unsigned a[4], const unsigned b[2]) {
    asm volatile(
        "mma.sync.aligned.m16n8k8.row.col.f32.tf32.tf32.f32 "
        "{%0,%1,%2,%3}, {%4,%5,%6,%7}, {%8,%9}, {%0,%1,%2,%3};"
        : "+f"(d[0]), "+f"(d[1]), "+f"(d[2]), "+f"(d[3])
        : "r"(a[0]), "r"(a[1]), "r"(a[2]), "r"(a[3]), "r"(b[0]), "r"(b[1]));
}

// ---------------- 0: W^T + tf32 convert (also resets counters) ----------------
__global__ void wtrans_kernel(const float* __restrict__ ew) {
    __shared__ float t[32][33];
    int e  = blockIdx.z;
    int k0 = blockIdx.x * 32, n0 = blockIdx.y * 32;
    int tx = threadIdx.x, ty = threadIdx.y;      // (32, 8)
    if (blockIdx.x == 0 && blockIdx.y == 0 && blockIdx.z == 0 && ty == 0 && tx < NE)
        g_count[tx] = 0;
    const float* src = ew + (size_t)e * DM * DM;
#pragma unroll
    for (int j = 0; j < 32; j += 8)
        t[ty + j][tx] = src[(size_t)(k0 + ty + j) * DM + n0 + tx];
    __syncthreads();
    unsigned* dst = g_wt + (size_t)e * DM * DM;
#pragma unroll
    for (int j = 0; j < 32; j += 8)
        dst[(size_t)(n0 + ty + j) * DM + k0 + tx] = f2tf32(t[tx][ty + j]);
}

// ---------------- 1: gating (warp per token, lean) ----------------
__global__ void gate_kernel(const float* __restrict__ x,
                            const float* __restrict__ wg) {
    __shared__ float sw[DM * NE];                 // 16 KB: w_gate [d][e]
    int tid = threadIdx.x;                        // 256
    for (int i = tid; i < DM * NE; i += 256) sw[i] = wg[i];
    __syncthreads();

    int warp = tid >> 5, lane = tid & 31;
    int token = blockIdx.x * 8 + warp;

    const float4* xr4 = (const float4*)(x + (size_t)token * DM);

    float acc[NE];
#pragma unroll
    for (int e = 0; e < NE; e++) acc[e] = 0.f;

#pragma unroll
    for (int i = 0; i < 4; i++) {
        int q = lane + i * 32;
        float4 v = xr4[q];
        int d = q * 4;
        const float* w0 = &sw[(d + 0) * NE];
        const float* w1 = &sw[(d + 1) * NE];
        const float* w2 = &sw[(d + 2) * NE];
        const float* w3 = &sw[(d + 3) * NE];
#pragma unroll
        for (int e = 0; e < NE; e++)
            acc[e] += v.x * w0[e] + v.y * w1[e] + v.z * w2[e] + v.w * w3[e];
    }
#pragma unroll
    for (int e = 0; e < NE; e++) {
#pragma unroll
        for (int off = 16; off > 0; off >>= 1)
            acc[e] += __shfl_xor_sync(0xFFFFFFFFu, acc[e], off);
    }
    if (lane == 0) {
        int i0 = 0; float v0 = acc[0];
#pragma unroll
        for (int e = 1; e < NE; e++) if (acc[e] > v0) { v0 = acc[e]; i0 = e; }
        int i1 = -1; float v1 = -3.0e38f;
#pragma unroll
        for (int e = 0; e < NE; e++) if (e != i0 && acc[e] > v1) { v1 = acc[e]; i1 = e; }
        float e1 = expf(v1 - v0);
        float inv = 1.f / (1.f + e1);
        g_eidx[token][0] = i0;  g_eidx[token][1] = i1;
        g_gate[token][0] = inv; g_gate[token][1] = e1 * inv;
        atomicAdd(&g_count[i0], 1);
        atomicAdd(&g_count[i1], 1);
    }
}

// ---------------- 2: scan + tile prefix (64-row m-tiles) ----------------
__global__ void scan_kernel() {
    if (threadIdx.x == 0) {
        int acc = 0, tacc = 0;
        for (int e = 0; e < NE; e++) {
            int c = g_count[e];
            g_offs[e] = acc; g_cursor[e] = acc; acc += c;
            g_ts[e] = tacc;  tacc += ((c + 63) >> 6) * (DM / 128);
        }
        g_ts[NE] = tacc;
        g_ntiles = tacc;
        g_tile_cursor = 0;
    }
}

// ---------------- 3: slot assignment (block-aggregated atomics) ----------------
__global__ void assign_kernel() {
    __shared__ int loc[NE], bbase[NE];
    int tid = threadIdx.x;
    if (tid < NE) loc[tid] = 0;
    __syncthreads();
    int n = blockIdx.x * 256 + tid;
    int e[TOPK], p[TOPK];
#pragma unroll
    for (int k = 0; k < TOPK; k++) {
        e[k] = g_eidx[n][k];
        p[k] = atomicAdd(&loc[e[k]], 1);
    }
    __syncthreads();
    if (tid < NE) bbase[tid] = atomicAdd(&g_cursor[tid], loc[tid]);
    __syncthreads();
#pragma unroll
    for (int k = 0; k < TOPK; k++) {
        int pos = bbase[e[k]] + p[k];
        g_tok[pos]   = n;
        g_slot[n][k] = pos;
    }
}

// ---------------- 4: PERSISTENT grouped GEMM, tf32 mma.sync, occ=3 ----------------
// CTA tile 64x128, 8 warps 2x4 (warp tile 32x32, acc=32 regs). Double-buffered smem;
// A: LDG->reg->cvt->STS prefetch; B: cp.async (g_wt, W^T tf32 [n][k]). LDW=36 words ->
// all frag LDS and A-STS conflict-free (R12-proven maps). Tiles popped from cursor.
#define MT       64
#define KTILE    32
#define LDW      36
#define ROW_B    (LDW * 4)                  // 144 bytes
#define A_BYTES  (MT  * ROW_B)              // 9216
#define B_BYTES  (128 * ROW_B)              // 18432
#define BUF_B    (A_BYTES + B_BYTES)        // 27648
#define DYN_SMEM (2 * BUF_B)                // 55296

__global__ void __launch_bounds__(256, 3)
expert_gemm(const float* __restrict__ x) {
    extern __shared__ __align__(16) char dyn[];
    __shared__ int s_t;

    const int tid  = threadIdx.x;   // 256
    const int lane = tid & 31;
    const int wid  = tid >> 5;
    const int wm   = (wid & 1) * 32;      // warp row origin (0/32)
    const int wn   = (wid >> 1) * 32;     // warp col origin (0..96)
    const int gr   = lane >> 2;
    const int gc   = lane & 3;

    // A map: row_a = tid>>2 (0..63), qa = tid&3 -> words qa*8..qa*8+7
    const int row_a = tid >> 2, qa = tid & 3;
    // B map: row_b = tid>>1 (0..127), hb = tid&1 -> words hb*16..hb*16+15
    const int row_b = tid >> 1, hb = tid & 1;

    const uint32_t sb = smem_u32(dyn);
    const uint32_t a_dst0 = sb + row_a * ROW_B + qa * 32;
    const uint32_t b_dst0 = sb + A_BYTES + row_b * ROW_B + hb * 64;

    const int ntiles = g_ntiles;

    for (;;) {
        if (tid == 0) s_t = atomicAdd(&g_tile_cursor, 1);
        __syncthreads();
        const int t = s_t;
        if (t >= ntiles) break;

        // ---- decode tile -> (expert, m0, n0) ----
        int e = 0;
        while (e < NE - 1 && t >= g_ts[e + 1]) e++;
        const int local = t - g_ts[e];
        const int m0 = (local >> 2) * MT;
        const int n0 = (local & 3) * 128;
        const int cnt  = g_count[e];
        const int base = g_offs[e];

        int rr = m0 + row_a; if (rr >= cnt) rr = cnt - 1;  // clamp; rows >= cnt never stored
        const float4* arow = (const float4*)(x + (size_t)g_tok[base + rr] * DM);
        const char*   brow = (const char*)(g_wt + ((size_t)e * DM + n0 + row_b) * DM) + hb * 64;

        float acc[2][4][4];
#pragma unroll
        for (int mi = 0; mi < 2; mi++)
#pragma unroll
            for (int ni = 0; ni < 4; ni++)
#pragma unroll
                for (int q = 0; q < 4; q++) acc[mi][ni][q] = 0.f;

        float4 av0, av1;
        // ---- prologue: k-tile 0 -> buffer 0 ----
#pragma unroll
        for (int j = 0; j < 4; j++) cp16(b_dst0 + j * 16, brow + j * 16);
        av0 = arow[qa * 2]; av1 = arow[qa * 2 + 1];
        {
            uint4 u0, u1;
            u0.x = f2tf32(av0.x); u0.y = f2tf32(av0.y); u0.z = f2tf32(av0.z); u0.w = f2tf32(av0.w);
            u1.x = f2tf32(av1.x); u1.y = f2tf32(av1.y); u1.z = f2tf32(av1.z); u1.w = f2tf32(av1.w);
            *(uint4*)(dyn + (a_dst0 - sb))      = u0;
            *(uint4*)(dyn + (a_dst0 - sb) + 16) = u1;
        }
        CP_COMMIT();
        CP_WAIT0();
        __syncthreads();

        const int NKT = DM / KTILE;     // 16
        for (int kt = 0; kt < NKT; kt++) {
            const bool hn = (kt + 1) < NKT;
            if (hn) {
                // B(kt+1) via cp.async into buffer (kt+1)&1
                const uint32_t bd = b_dst0 + ((kt + 1) & 1) * BUF_B;
                const char* bs = brow + (kt + 1) * (KTILE * 4);
#pragma unroll
                for (int j = 0; j < 4; j++) cp16(bd + j * 16, bs + j * 16);
                CP_COMMIT();
                // A(kt+1) into registers
                const int o = (kt + 1) * 8 + qa * 2;
                av0 = arow[o]; av1 = arow[o + 1];
            }

            // ---- compute k-tile kt from buffer kt&1 ----
            const unsigned* Ab = (const unsigned*)(dyn + (kt & 1) * BUF_B);
            const unsigned* Bb = (const unsigned*)(dyn + (kt & 1) * BUF_B + A_BYTES);
#pragma unroll
            for (int s = 0; s < 4; s++) {
                const int kb = s * 8;
                unsigned a[2][4], b[4][2];
#pragma unroll
                for (int mi = 0; mi < 2; mi++) {
                    const unsigned* r0 = Ab + (wm + mi * 16 + gr) * LDW;
                    const unsigned* r1 = r0 + 8 * LDW;
                    a[mi][0] = r0[kb + gc];
                    a[mi][1] = r1[kb + gc];
                    a[mi][2] = r0[kb + gc + 4];
                    a[mi][3] = r1[kb + gc + 4];
                }
#pragma unroll
                for (int ni = 0; ni < 4; ni++) {
                    const unsigned* rb = Bb + (wn + ni * 8 + gr) * LDW;
                    b[ni][0] = rb[kb + gc];
                    b[ni][1] = rb[kb + gc + 4];
                }
#pragma unroll
                for (int mi = 0; mi < 2; mi++)
#pragma unroll
                    for (int ni = 0; ni < 4; ni++)
                        mma_tf32(acc[mi][ni], a[mi], b[ni]);
            }

            if (hn) {
                // commit prefetched A to buffer (kt+1)&1; wait B; one barrier
                uint32_t ad = a_dst0 + ((kt + 1) & 1) * BUF_B - sb;
                uint4 u0, u1;
                u0.x = f2tf32(av0.x); u0.y = f2tf32(av0.y); u0.z = f2tf32(av0.z); u0.w = f2tf32(av0.w);
                u1.x = f2tf32(av1.x); u1.y = f2tf32(av1.y); u1.z = f2tf32(av1.z); u1.w = f2tf32(av1.w);
                *(uint4*)(dyn + ad)      = u0;
                *(uint4*)(dyn + ad + 16) = u1;
                CP_WAIT0();
                __syncthreads();
            }
        }

        // ---- epilogue ----
#pragma unroll
        for (int mi = 0; mi < 2; mi++) {
            int r0 = m0 + wm + mi * 16 + gr;
            int r1 = r0 + 8;
#pragma unroll
            for (int ni = 0; ni < 4; ni++) {
                int c = n0 + wn + ni * 8 + 2 * gc;
                if (r0 < cnt)
                    *(float2*)(g_y + (size_t)(base + r0) * DM + c) =
                        make_float2(acc[mi][ni][0], acc[mi][ni][1]);
                if (r1 < cnt)
                    *(float2*)(g_y + (size_t)(base + r1) * DM + c) =
                        make_float2(acc[mi][ni][2], acc[mi][ni][3]);
            }
        }
    }
}

// ---------------- 5: log-domain combine (token per block, float4) ----------------
__device__ __forceinline__ float comb1(float g0, float g1, float ya, float yb) {
    float c = g0 * __expf(ya) + g1 * __expf(yb);
    if (c == 0.f) c = 2.220446049250313e-16f;
    return __logf(c);
}
__global__ void combine_kernel(float* __restrict__ out) {
    int n = blockIdx.x;
    float g0 = g_gate[n][0], g1 = g_gate[n][1];
    const float4* y0 = (const float4*)(g_y + (size_t)g_slot[n][0] * DM);
    const float4* y1 = (const float4*)(g_y + (size_t)g_slot[n][1] * DM);
    float4* o = (float4*)(out + (size_t)n * DM);
    int f = threadIdx.x;                  // 128 threads * float4 = 512
    float4 a = y0[f], b = y1[f];
    float4 r;
    r.x = comb1(g0, g1, a.x, b.x);
    r.y = comb1(g0, g1, a.y, b.y);
    r.z = comb1(g0, g1, a.z, b.z);
    r.w = comb1(g0, g1, a.w, b.w);
    o[f] = r;
}

// ---------------- 6: balance loss (deterministic reduction) ----------------
__global__ void loss_kernel(float* __restrict__ out, int out_size) {
    __shared__ float s[NE][256];
    int tid = threadIdx.x;
    float imp[NE];
#pragma unroll
    for (int e = 0; e < NE; e++) imp[e] = 0.f;
    for (int n = tid; n < NTOK; n += 256) {
#pragma unroll
        for (int k = 0; k < TOPK; k++)
            imp[g_eidx[n][k]] += g_gate[n][k];
    }
#pragma unroll
    for (int e = 0; e < NE; e++) s[e][tid] = imp[e];
    __syncthreads();
    for (int st = 128; st > 0; st >>= 1) {
        if (tid < st) {
#pragma unroll
            for (int e = 0; e < NE; e++) s[e][tid] += s[e][tid + st];
        }
        __syncthreads();
    }
    if (tid == 0) {
        float mi = 0.f, ml = 0.f, iv[NE], lv[NE];
        for (int e = 0; e < NE; e++) {
            iv[e] = s[e][0]; lv[e] = (float)g_count[e];
            mi += iv[e]; ml += lv[e];
        }
        mi *= (1.f / NE); ml *= (1.f / NE);
        float vi = 0.f, vl = 0.f;
        for (int e = 0; e < NE; e++) {
            float di = iv[e] - mi, dl = lv[e] - ml;
            vi += di * di; vl += dl * dl;
        }
        vi *= (1.f / NE); vl *= (1.f / NE);
        float loss = vi / (mi * mi + 1e-10f) + vl / (ml * ml + 1e-10f);
        if (out_size > NTOK * DM) out[NTOK * DM] = loss;
    }
}

// ---------------- launch ----------------
extern "C" void kernel_launch(void* const* d_in, const int* in_sizes, int n_in,
                              void* d_out, int out_size) {
    const float* x  = (const float*)d_in[0];   // [8192, 512]
    const float* wg = (const float*)d_in[1];   // [512, 8]
    const float* ew = (const float*)d_in[2];   // [8, 512, 512]
    float* out = (float*)d_out;

    static int attr_done = 0;
    if (!attr_done) {
        cudaFuncSetAttribute(expert_gemm, cudaFuncAttributeMaxDynamicSharedMemorySize, DYN_SMEM);
        attr_done = 1;
    }

    {
        dim3 g(DM / 32, DM / 32, NE);
        wtrans_kernel<<<g, dim3(32, 8)>>>(ew);      // W^T tf32 + counter reset
    }
    gate_kernel<<<NTOK / 8, 256>>>(x, wg);
    scan_kernel<<<1, 32>>>();
    assign_kernel<<<NTOK / 256, 256>>>();
    expert_gemm<<<444, 256, DYN_SMEM>>>(x);         // persistent, 3 CTAs/SM target
    combine_kernel<<<NTOK, 128>>>(out);
    loss_kernel<<<1, 256>>>(out, out_size);
}

// round 16
// speedup vs baseline: 1.0219x; 1.0219x over previous
#include <cuda_runtime.h>
#include <math.h>
#include <stdint.h>

#define NTOK 8192
#define DM   512
#define NE   8
#define TOPK 2
#define NASSIGN (NTOK * TOPK)

// ---------------- scratch (device globals: no allocation allowed) ----------------
__device__ int   g_count[NE];
__device__ int   g_offs[NE];
__device__ int   g_cursor[NE];
__device__ int   g_ts[NE + 1];                  // tile prefix per expert (MT=64 tiles)
__device__ int   g_ntiles;
__device__ int   g_tile_cursor;
__device__ int   g_eidx[NTOK][TOPK];
__device__ float g_gate[NTOK][TOPK];
__device__ int   g_tok[NASSIGN];
__device__ int   g_slot[NTOK][TOPK];
__device__ float g_y[(size_t)NASSIGN * DM];     // 32 MB expert-output scratch

// ---------------- helpers ----------------
__device__ __forceinline__ unsigned f2tf32(float f) {
    unsigned u;
    asm("cvt.rna.tf32.f32 %0, %1;" : "=r"(u) : "f"(f));
    return u;
}
__device__ __forceinline__ void mma_tf32(float d[4], const unsigned a[4], const unsigned b[2]) {
    asm volatile(
        "mma.sync.aligned.m16n8k8.row.col.f32.tf32.tf32.f32 "
        "{%0,%1,%2,%3}, {%4,%5,%6,%7}, {%8,%9}, {%0,%1,%2,%3};"
        : "+f"(d[0]), "+f"(d[1]), "+f"(d[2]), "+f"(d[3])
        : "r"(a[0]), "r"(a[1]), "r"(a[2]), "r"(a[3]), "r"(b[0]), "r"(b[1]));
}

// ---------------- 0: reset counters ----------------
__global__ void init_kernel() {
    int t = threadIdx.x;
    if (t < NE) g_count[t] = 0;
}

// ---------------- 1: gating (warp per token, lean) ----------------
__global__ void gate_kernel(const float* __restrict__ x,
                            const float* __restrict__ wg) {
    __shared__ float sw[DM * NE];                 // 16 KB: w_gate [d][e]
    int tid = threadIdx.x;                        // 256
    for (int i = tid; i < DM * NE; i += 256) sw[i] = wg[i];
    __syncthreads();

    int warp = tid >> 5, lane = tid & 31;
    int token = blockIdx.x * 8 + warp;

    const float4* xr4 = (const float4*)(x + (size_t)token * DM);

    float acc[NE];
#pragma unroll
    for (int e = 0; e < NE; e++) acc[e] = 0.f;

#pragma unroll
    for (int i = 0; i < 4; i++) {
        int q = lane + i * 32;
        float4 v = xr4[q];
        int d = q * 4;
        const float* w0 = &sw[(d + 0) * NE];
        const float* w1 = &sw[(d + 1) * NE];
        const float* w2 = &sw[(d + 2) * NE];
        const float* w3 = &sw[(d + 3) * NE];
#pragma unroll
        for (int e = 0; e < NE; e++)
            acc[e] += v.x * w0[e] + v.y * w1[e] + v.z * w2[e] + v.w * w3[e];
    }
#pragma unroll
    for (int e = 0; e < NE; e++) {
#pragma unroll
        for (int off = 16; off > 0; off >>= 1)
            acc[e] += __shfl_xor_sync(0xFFFFFFFFu, acc[e], off);
    }
    if (lane == 0) {
        int i0 = 0; float v0 = acc[0];
#pragma unroll
        for (int e = 1; e < NE; e++) if (acc[e] > v0) { v0 = acc[e]; i0 = e; }
        int i1 = -1; float v1 = -3.0e38f;
#pragma unroll
        for (int e = 0; e < NE; e++) if (e != i0 && acc[e] > v1) { v1 = acc[e]; i1 = e; }
        float e1 = expf(v1 - v0);
        float inv = 1.f / (1.f + e1);
        g_eidx[token][0] = i0;  g_eidx[token][1] = i1;
        g_gate[token][0] = inv; g_gate[token][1] = e1 * inv;
        atomicAdd(&g_count[i0], 1);
        atomicAdd(&g_count[i1], 1);
    }
}

// ---------------- 2: scan + tile prefix (MT=64 m-tiles, 4 n-tiles) ----------------
__global__ void scan_kernel() {
    if (threadIdx.x == 0) {
        int acc = 0, tacc = 0;
        for (int e = 0; e < NE; e++) {
            int c = g_count[e];
            g_offs[e] = acc; g_cursor[e] = acc; acc += c;
            g_ts[e] = tacc;  tacc += ((c + 63) >> 6) * (DM / 128);
        }
        g_ts[NE] = tacc;
        g_ntiles = tacc;
        g_tile_cursor = 0;
    }
}

// ---------------- 3: slot assignment (block-aggregated atomics) ----------------
__global__ void assign_kernel() {
    __shared__ int loc[NE], bbase[NE];
    int tid = threadIdx.x;
    if (tid < NE) loc[tid] = 0;
    __syncthreads();
    int n = blockIdx.x * 256 + tid;
    int e[TOPK], p[TOPK];
#pragma unroll
    for (int k = 0; k < TOPK; k++) {
        e[k] = g_eidx[n][k];
        p[k] = atomicAdd(&loc[e[k]], 1);
    }
    __syncthreads();
    if (tid < NE) bbase[tid] = atomicAdd(&g_cursor[tid], loc[tid]);
    __syncthreads();
#pragma unroll
    for (int k = 0; k < TOPK; k++) {
        int pos = bbase[e[k]] + p[k];
        g_tok[pos]   = n;
        g_slot[n][k] = pos;
    }
}

// ---------------- 4: PERSISTENT grouped GEMM, tf32 mma.sync, occ=3 ----------------
// CTA tile 64x128, 8 warps 2x4 (warp tile 32x32, acc = 32 regs). KTILE=16.
// A [m][k] stride 20 (conflict-free frag LDS & STS); B [k][n] stride 132 (R6-proven
// maps), loaded straight from ew with cvt.rna in registers. Pure LDG->reg->STS
// double buffer, ONE __syncthreads per k-iter. Tiles popped from global cursor.
#define MT     64
#define KT16   16
#define LDA    20      // words per A row
#define LDB    132     // words per B k-row

__global__ void __launch_bounds__(256, 3)
expert_gemm(const float* __restrict__ x, const float* __restrict__ ew) {
    __shared__ unsigned As[2][MT][LDA];     // 10240 B
    __shared__ unsigned Bs[2][KT16][LDB];   // 16896 B
    __shared__ int s_t;

    const int tid  = threadIdx.x;   // 256
    const int lane = tid & 31;
    const int wid  = tid >> 5;
    const int wm   = (wid & 1) * 32;      // warp row origin
    const int wn   = (wid >> 1) * 32;     // warp col origin
    const int gr   = lane >> 2;
    const int gc   = lane & 3;

    // A load map: row_a = tid>>2 (0..63), qa = (tid&3)*4 -> one float4 per thread
    const int row_a = tid >> 2, qa = (tid & 3) * 4;
    // B load map: k-row br = tid>>5 (0..7) + {0,8}, col bc = (tid&31)*4
    const int br = tid >> 5, bc = (tid & 31) * 4;

    const int ntiles = g_ntiles;

    for (;;) {
        if (tid == 0) s_t = atomicAdd(&g_tile_cursor, 1);
        __syncthreads();
        const int t = s_t;
        if (t >= ntiles) break;

        // ---- decode tile -> (expert, m0, n0) ----
        int e = 0;
        while (e < NE - 1 && t >= g_ts[e + 1]) e++;
        const int local = t - g_ts[e];
        const int m0 = (local >> 2) * MT;
        const int n0 = (local & 3) * 128;
        const int cnt  = g_count[e];
        const int base = g_offs[e];

        int rr = m0 + row_a; if (rr >= cnt) rr = cnt - 1;   // clamp; rows >= cnt never stored
        const float* arow = x + (size_t)g_tok[base + rr] * DM + qa;
        const float* W    = ew + (size_t)e * DM * DM + n0 + bc;

        float acc[2][4][4];
#pragma unroll
        for (int mi = 0; mi < 2; mi++)
#pragma unroll
            for (int ni = 0; ni < 4; ni++)
#pragma unroll
                for (int q = 0; q < 4; q++) acc[mi][ni][q] = 0.f;

        float4 av, bv[2];
        // ---- prologue: k-tile 0 -> buffer 0 ----
        av = *(const float4*)(arow);
#pragma unroll
        for (int i = 0; i < 2; i++)
            bv[i] = *(const float4*)(W + (size_t)(br + i * 8) * DM);
        {
            unsigned* dA = &As[0][row_a][qa];
            dA[0] = f2tf32(av.x); dA[1] = f2tf32(av.y);
            dA[2] = f2tf32(av.z); dA[3] = f2tf32(av.w);
#pragma unroll
            for (int i = 0; i < 2; i++) {
                unsigned* dB = &Bs[0][br + i * 8][bc];
                dB[0] = f2tf32(bv[i].x); dB[1] = f2tf32(bv[i].y);
                dB[2] = f2tf32(bv[i].z); dB[3] = f2tf32(bv[i].w);
            }
        }
        __syncthreads();

        const int NKT = DM / KT16;      // 32
        for (int kt = 0; kt < NKT; kt++) {
            const bool hn = (kt + 1) < NKT;
            // ---- prefetch k-tile kt+1 into registers (overlaps mma) ----
            if (hn) {
                const int k0n = (kt + 1) * KT16;
                av = *(const float4*)(arow + k0n);
#pragma unroll
                for (int i = 0; i < 2; i++)
                    bv[i] = *(const float4*)(W + (size_t)(k0n + br + i * 8) * DM);
            }

            // ---- compute k-tile kt from buffer kt&1 ----
            const int bsel = kt & 1;
#pragma unroll
            for (int s = 0; s < 2; s++) {
                const int kb = s * 8;
                unsigned a[2][4], b[4][2];
#pragma unroll
                for (int mi = 0; mi < 2; mi++) {
                    const unsigned* r0 = As[bsel][wm + mi * 16 + gr];
                    const unsigned* r1 = As[bsel][wm + mi * 16 + gr + 8];
                    a[mi][0] = r0[kb + gc];
                    a[mi][1] = r1[kb + gc];
                    a[mi][2] = r0[kb + gc + 4];
                    a[mi][3] = r1[kb + gc + 4];
                }
#pragma unroll
                for (int ni = 0; ni < 4; ni++) {
                    b[ni][0] = Bs[bsel][kb + gc][wn + ni * 8 + gr];
                    b[ni][1] = Bs[bsel][kb + gc + 4][wn + ni * 8 + gr];
                }
#pragma unroll
                for (int mi = 0; mi < 2; mi++)
#pragma unroll
                    for (int ni = 0; ni < 4; ni++)
                        mma_tf32(acc[mi][ni], a[mi], b[ni]);
            }

            // ---- commit prefetched regs to buffer (kt+1)&1; single barrier ----
            if (hn) {
                const int nsel = (kt + 1) & 1;
                unsigned* dA = &As[nsel][row_a][qa];
                dA[0] = f2tf32(av.x); dA[1] = f2tf32(av.y);
                dA[2] = f2tf32(av.z); dA[3] = f2tf32(av.w);
#pragma unroll
                for (int i = 0; i < 2; i++) {
                    unsigned* dB = &Bs[nsel][br + i * 8][bc];
                    dB[0] = f2tf32(bv[i].x); dB[1] = f2tf32(bv[i].y);
                    dB[2] = f2tf32(bv[i].z); dB[3] = f2tf32(bv[i].w);
                }
                __syncthreads();
            }
        }

        // ---- epilogue: d0/d1 -> (row, 2c), d2/d3 -> (row+8, 2c) ----
#pragma unroll
        for (int mi = 0; mi < 2; mi++) {
            int r0 = m0 + wm + mi * 16 + gr;
            int r1 = r0 + 8;
#pragma unroll
            for (int ni = 0; ni < 4; ni++) {
                int c = n0 + wn + ni * 8 + 2 * gc;
                if (r0 < cnt)
                    *(float2*)(g_y + (size_t)(base + r0) * DM + c) =
                        make_float2(acc[mi][ni][0], acc[mi][ni][1]);
                if (r1 < cnt)
                    *(float2*)(g_y + (size_t)(base + r1) * DM + c) =
                        make_float2(acc[mi][ni][2], acc[mi][ni][3]);
            }
        }
        __syncthreads();    // all reads of As/Bs done before next tile's prologue writes
    }
}

// ---------------- 5: log-domain combine (token per block, float4) ----------------
__device__ __forceinline__ float comb1(float g0, float g1, float ya, float yb) {
    float c = g0 * __expf(ya) + g1 * __expf(yb);
    if (c == 0.f) c = 2.220446049250313e-16f;
    return __logf(c);
}
__global__ void combine_kernel(float* __restrict__ out) {
    int n = blockIdx.x;
    float g0 = g_gate[n][0], g1 = g_gate[n][1];
    const float4* y0 = (const float4*)(g_y + (size_t)g_slot[n][0] * DM);
    const float4* y1 = (const float4*)(g_y + (size_t)g_slot[n][1] * DM);
    float4* o = (float4*)(out + (size_t)n * DM);
    int f = threadIdx.x;                  // 128 threads * float4 = 512
    float4 a = y0[f], b = y1[f];
    float4 r;
    r.x = comb1(g0, g1, a.x, b.x);
    r.y = comb1(g0, g1, a.y, b.y);
    r.z = comb1(g0, g1, a.z, b.z);
    r.w = comb1(g0, g1, a.w, b.w);
    o[f] = r;
}

// ---------------- 6: balance loss (deterministic reduction) ----------------
__global__ void loss_kernel(float* __restrict__ out, int out_size) {
    __shared__ float s[NE][256];
    int tid = threadIdx.x;
    float imp[NE];
#pragma unroll
    for (int e = 0; e < NE; e++) imp[e] = 0.f;
    for (int n = tid; n < NTOK; n += 256) {
#pragma unroll
        for (int k = 0; k < TOPK; k++)
            imp[g_eidx[n][k]] += g_gate[n][k];
    }
#pragma unroll
    for (int e = 0; e < NE; e++) s[e][tid] = imp[e];
    __syncthreads();
    for (int st = 128; st > 0; st >>= 1) {
        if (tid < st) {
#pragma unroll
            for (int e = 0; e < NE; e++) s[e][tid] += s[e][tid + st];
        }
        __syncthreads();
    }
    if (tid == 0) {
        float mi = 0.f, ml = 0.f, iv[NE], lv[NE];
        for (int e = 0; e < NE; e++) {
            iv[e] = s[e][0]; lv[e] = (float)g_count[e];
            mi += iv[e]; ml += lv[e];
        }
        mi *= (1.f / NE); ml *= (1.f / NE);
        float vi = 0.f, vl = 0.f;
        for (int e = 0; e < NE; e++) {
            float di = iv[e] - mi, dl = lv[e] - ml;
            vi += di * di; vl += dl * dl;
        }
        vi *= (1.f / NE); vl *= (1.f / NE);
        float loss = vi / (mi * mi + 1e-10f) + vl / (ml * ml + 1e-10f);
        if (out_size > NTOK * DM) out[NTOK * DM] = loss;
    }
}

// ---------------- launch ----------------
extern "C" void kernel_launch(void* const* d_in, const int* in_sizes, int n_in,
                              void* d_out, int out_size) {
    const float* x  = (const float*)d_in[0];   // [8192, 512]
    const float* wg = (const float*)d_in[1];   // [512, 8]
    const float* ew = (const float*)d_in[2];   // [8, 512, 512]
    float* out = (float*)d_out;

    init_kernel<<<1, 32>>>();
    gate_kernel<<<NTOK / 8, 256>>>(x, wg);
    scan_kernel<<<1, 32>>>();
    assign_kernel<<<NTOK / 256, 256>>>();
    expert_gemm<<<444, 256>>>(x, ew);            // persistent, 3 CTAs/SM
    combine_kernel<<<NTOK, 128>>>(out);
    loss_kernel<<<1, 256>>>(out, out_size);
}